// round 1
// baseline (speedup 1.0000x reference)
#include <cuda_runtime.h>

#define NPTS 262144
#define CCLS 10
#define DFEAT 64
#define TTRI 4096

__global__ void zero_out_kernel(float* out) {
    if (threadIdx.x == 0) out[0] = 0.0f;
}

__global__ void __launch_bounds__(256) fused_loss_kernel(
    const float* __restrict__ gt_img,
    const float* __restrict__ gt_seg,
    const float* __restrict__ inr_output,
    const float* __restrict__ seg_output,
    const float* __restrict__ inr_features,
    const int* __restrict__ a_idx,
    const int* __restrict__ p_idx,
    const int* __restrict__ n_idx,
    float* __restrict__ out)
{
    const int tid    = blockIdx.x * blockDim.x + threadIdx.x;
    const int stride = gridDim.x * blockDim.x;
    const int lane   = threadIdx.x & 31;

    float acc = 0.0f;

    // ---------------- MSE: mean((inr_output - gt_img)^2) over 3N floats ---
    {
        const float4* io4 = (const float4*)inr_output;
        const float4* gi4 = (const float4*)gt_img;
        const int n4 = (NPTS * 3) / 4;   // 196608, exact
        float mse = 0.0f;
        for (int i = tid; i < n4; i += stride) {
            float4 a = io4[i];
            float4 b = gi4[i];
            float dx = a.x - b.x, dy = a.y - b.y, dz = a.z - b.z, dw = a.w - b.w;
            mse += dx * dx + dy * dy + dz * dz + dw * dw;
        }
        acc += mse * (1.0f / (float)(NPTS * 3));
    }

    // ---------------- CE: -mean_row( sum_c gt*logsoftmax(x) ) -------------
    {
        float ce = 0.0f;
        for (int row = tid; row < NPTS; row += stride) {
            const float2* x2 = (const float2*)(seg_output + (size_t)row * CCLS);
            const float2* g2 = (const float2*)(gt_seg     + (size_t)row * CCLS);
            float x[CCLS], g[CCLS];
            #pragma unroll
            for (int j = 0; j < CCLS / 2; j++) {
                float2 v = x2[j]; x[2 * j] = v.x; x[2 * j + 1] = v.y;
                float2 w = g2[j]; g[2 * j] = w.x; g[2 * j + 1] = w.y;
            }
            float m = x[0];
            #pragma unroll
            for (int c = 1; c < CCLS; c++) m = fmaxf(m, x[c]);
            float se = 0.0f, dot = 0.0f, gs = 0.0f;
            #pragma unroll
            for (int c = 0; c < CCLS; c++) {
                se  += __expf(x[c] - m);
                dot += g[c] * x[c];
                gs  += g[c];
            }
            float lse = __logf(se);
            // -sum_c g*(x - m - lse) = gs*(m+lse) - dot
            ce += gs * (m + lse) - dot;
        }
        acc += ce * (1.0f / (float)NPTS);
    }

    // ---------------- Triplet: warp per triplet ---------------------------
    {
        const int gwarp   = tid >> 5;
        const int wstride = stride >> 5;
        float tl = 0.0f;
        for (int t = gwarp; t < TTRI; t += wstride) {
            const float2* a = (const float2*)(inr_features + (size_t)a_idx[t] * DFEAT);
            const float2* p = (const float2*)(inr_features + (size_t)p_idx[t] * DFEAT);
            const float2* n = (const float2*)(inr_features + (size_t)n_idx[t] * DFEAT);
            float2 av = a[lane], pv = p[lane], nv = n[lane];
            float dpx = av.x - pv.x, dpy = av.y - pv.y;
            float dnx = av.x - nv.x, dny = av.y - nv.y;
            float dp = dpx * dpx + dpy * dpy;
            float dn = dnx * dnx + dny * dny;
            #pragma unroll
            for (int o = 16; o > 0; o >>= 1) {
                dp += __shfl_xor_sync(0xffffffff, dp, o);
                dn += __shfl_xor_sync(0xffffffff, dn, o);
            }
            if (lane == 0) tl += fmaxf(sqrtf(dp) - sqrtf(dn), 0.0f);
        }
        acc += tl;
    }

    // ---------------- Block reduce + one atomic per block -----------------
    __shared__ float sm[32];
    #pragma unroll
    for (int o = 16; o > 0; o >>= 1)
        acc += __shfl_xor_sync(0xffffffff, acc, o);
    const int wid = threadIdx.x >> 5;
    if (lane == 0) sm[wid] = acc;
    __syncthreads();
    if (wid == 0) {
        float v = (lane < (blockDim.x >> 5)) ? sm[lane] : 0.0f;
        #pragma unroll
        for (int o = 16; o > 0; o >>= 1)
            v += __shfl_xor_sync(0xffffffff, v, o);
        if (lane == 0) atomicAdd(out, v);
    }
}

extern "C" void kernel_launch(void* const* d_in, const int* in_sizes, int n_in,
                              void* d_out, int out_size) {
    const float* gt_img       = (const float*)d_in[0];
    const float* gt_seg       = (const float*)d_in[1];
    const float* inr_output   = (const float*)d_in[2];
    const float* seg_output   = (const float*)d_in[3];
    const float* inr_features = (const float*)d_in[4];
    const int*   a_idx        = (const int*)d_in[5];
    const int*   p_idx        = (const int*)d_in[6];
    const int*   n_idx        = (const int*)d_in[7];
    float* out = (float*)d_out;

    zero_out_kernel<<<1, 32>>>(out);
    fused_loss_kernel<<<512, 256>>>(gt_img, gt_seg, inr_output, seg_output,
                                    inr_features, a_idx, p_idx, n_idx, out);
}

// round 2
// speedup vs baseline: 1.1173x; 1.1173x over previous
#include <cuda_runtime.h>

#define NPTS 262144
#define CCLS 10
#define DFEAT 64
#define TTRI 4096

#define NBLK 1184   // 148 SMs * 8 CTAs
#define NTHR 256

__global__ void __launch_bounds__(NTHR, 8) fused_loss_kernel(
    const float* __restrict__ gt_img,
    const float* __restrict__ gt_seg,
    const float* __restrict__ inr_output,
    const float* __restrict__ seg_output,
    const float* __restrict__ inr_features,
    const int* __restrict__ a_idx,
    const int* __restrict__ p_idx,
    const int* __restrict__ n_idx,
    float* __restrict__ out)
{
    const int tid    = blockIdx.x * blockDim.x + threadIdx.x;
    const int stride = gridDim.x * blockDim.x;
    const int lane   = threadIdx.x & 31;

    float acc = 0.0f;

    // ---------------- MSE: mean((inr_output - gt_img)^2) over 3N floats ---
    {
        const float4* io4 = (const float4*)inr_output;
        const float4* gi4 = (const float4*)gt_img;
        const int n4 = (NPTS * 3) / 4;   // 196608, exact
        float mse = 0.0f;
        for (int i = tid; i < n4; i += stride) {
            float4 a = io4[i];
            float4 b = gi4[i];
            float dx = a.x - b.x, dy = a.y - b.y, dz = a.z - b.z, dw = a.w - b.w;
            mse += dx * dx + dy * dy + dz * dz + dw * dw;
        }
        acc += mse * (1.0f / (float)(NPTS * 3));
    }

    // ---------------- CE: -mean_row( sum_c gt*logsoftmax(x) ) -------------
    {
        float ce = 0.0f;
        for (int row = tid; row < NPTS; row += stride) {
            const float2* x2 = (const float2*)(seg_output + (size_t)row * CCLS);
            const float2* g2 = (const float2*)(gt_seg     + (size_t)row * CCLS);
            float x[CCLS], g[CCLS];
            #pragma unroll
            for (int j = 0; j < CCLS / 2; j++) {
                float2 v = x2[j]; x[2 * j] = v.x; x[2 * j + 1] = v.y;
                float2 w = g2[j]; g[2 * j] = w.x; g[2 * j + 1] = w.y;
            }
            float m = x[0];
            #pragma unroll
            for (int c = 1; c < CCLS; c++) m = fmaxf(m, x[c]);
            float se = 0.0f, dot = 0.0f, gs = 0.0f;
            #pragma unroll
            for (int c = 0; c < CCLS; c++) {
                se  += __expf(x[c] - m);
                dot += g[c] * x[c];
                gs  += g[c];
            }
            float lse = __logf(se);
            // -sum_c g*(x - m - lse) = gs*(m+lse) - dot
            ce += gs * (m + lse) - dot;
        }
        acc += ce * (1.0f / (float)NPTS);
    }

    // ---------------- Triplet: warp per triplet ---------------------------
    {
        const int gwarp   = tid >> 5;
        const int wstride = stride >> 5;
        float tl = 0.0f;
        for (int t = gwarp; t < TTRI; t += wstride) {
            const float2* a = (const float2*)(inr_features + (size_t)a_idx[t] * DFEAT);
            const float2* p = (const float2*)(inr_features + (size_t)p_idx[t] * DFEAT);
            const float2* n = (const float2*)(inr_features + (size_t)n_idx[t] * DFEAT);
            float2 av = a[lane], pv = p[lane], nv = n[lane];
            float dpx = av.x - pv.x, dpy = av.y - pv.y;
            float dnx = av.x - nv.x, dny = av.y - nv.y;
            float dp = dpx * dpx + dpy * dpy;
            float dn = dnx * dnx + dny * dny;
            #pragma unroll
            for (int o = 16; o > 0; o >>= 1) {
                dp += __shfl_xor_sync(0xffffffff, dp, o);
                dn += __shfl_xor_sync(0xffffffff, dn, o);
            }
            if (lane == 0) tl += fmaxf(sqrtf(dp) - sqrtf(dn), 0.0f);
        }
        acc += tl;
    }

    // ---------------- Block reduce + one atomic per block -----------------
    __shared__ float sm[32];
    #pragma unroll
    for (int o = 16; o > 0; o >>= 1)
        acc += __shfl_xor_sync(0xffffffff, acc, o);
    const int wid = threadIdx.x >> 5;
    if (lane == 0) sm[wid] = acc;
    __syncthreads();
    if (wid == 0) {
        float v = (lane < (blockDim.x >> 5)) ? sm[lane] : 0.0f;
        #pragma unroll
        for (int o = 16; o > 0; o >>= 1)
            v += __shfl_xor_sync(0xffffffff, v, o);
        if (lane == 0) atomicAdd(out, v);
    }
}

extern "C" void kernel_launch(void* const* d_in, const int* in_sizes, int n_in,
                              void* d_out, int out_size) {
    const float* gt_img       = (const float*)d_in[0];
    const float* gt_seg       = (const float*)d_in[1];
    const float* inr_output   = (const float*)d_in[2];
    const float* seg_output   = (const float*)d_in[3];
    const float* inr_features = (const float*)d_in[4];
    const int*   a_idx        = (const int*)d_in[5];
    const int*   p_idx        = (const int*)d_in[6];
    const int*   n_idx        = (const int*)d_in[7];
    float* out = (float*)d_out;

    cudaMemsetAsync(out, 0, sizeof(float));
    fused_loss_kernel<<<NBLK, NTHR>>>(gt_img, gt_seg, inr_output, seg_output,
                                      inr_features, a_idx, p_idx, n_idx, out);
}